// round 7
// baseline (speedup 1.0000x reference)
#include <cuda_runtime.h>
#include <cstdint>

#define NN 8192
#define NCHUNK (NN / 32)      // 256 chunks of 32 candidates
#define KB 4096               // histogram buckets

// Scratch (device globals — no allocation allowed in kernel_launch).
// Every array is fully rewritten each launch -> graph-replay deterministic.
__device__ float g_s[NN];        // s[j] by original index
__device__ float g_wm[NN];       // wmax[j] by original index
__device__ int   g_bk[NN];       // bucket id by original index
__device__ int   g_hist[KB];     // bucket histogram
__device__ int   g_cur[KB];      // bucket exclusive offsets -> scatter cursors
__device__ float g_ss[NN];       // s in bucket-sorted order
__device__ float g_ws[NN];       // wmax in bucket-sorted order
__device__ int   g_idx[NN];      // original index in bucket-sorted order
__device__ float g_cmin[NCHUNK]; // suffix min of s over chunks >= c
__device__ float g_cwub[NCHUNK]; // suffix max of wmax over chunks >= c
__device__ float g_cnsw[NCHUNK]; // suffix max of (-s*w) over chunks >= c

// K0: zero histogram (replays must not see stale counts)
__global__ void zero_hist_kernel() {
    g_hist[blockIdx.x * blockDim.x + threadIdx.x] = 0;
}

// K1: per-element s, wmax, bucket; histogram via spread global atomics (REDG)
__global__ __launch_bounds__(256)
void bucket_kernel(const float* __restrict__ x, const float* __restrict__ Wphi) {
    int j = blockIdx.x * 256 + threadIdx.x;
    float s = x[3 * j + 0] + x[3 * j + 1] + x[3 * j + 2];
    float w0 = Wphi[j], w1 = Wphi[NN + j], w2 = Wphi[2 * NN + j];
    float w = fmaxf(w0, fmaxf(w1, w2));
    int b = (int)(s * (KB / 3.0f));
    b = max(0, min(KB - 1, b));
    g_s[j]  = s;
    g_wm[j] = w;
    g_bk[j] = b;
    atomicAdd(&g_hist[b], 1);
}

// K2: exclusive scan of g_hist[4096] -> g_cur (hierarchical warp-shuffle scan)
__global__ __launch_bounds__(1024)
void scan_kernel() {
    __shared__ int warpsums[32];
    const int t = threadIdx.x, lane = t & 31, wid = t >> 5;

    int4 h = reinterpret_cast<const int4*>(g_hist)[t];   // buckets 4t..4t+3
    int lsum = h.x + h.y + h.z + h.w;
    int inc = lsum;
    #pragma unroll
    for (int off = 1; off < 32; off <<= 1) {
        int n = __shfl_up_sync(0xffffffffu, inc, off);
        if (lane >= off) inc += n;
    }
    if (lane == 31) warpsums[wid] = inc;
    __syncthreads();
    if (wid == 0) {
        int ws = warpsums[lane];
        int winc = ws;
        #pragma unroll
        for (int off = 1; off < 32; off <<= 1) {
            int n = __shfl_up_sync(0xffffffffu, winc, off);
            if (lane >= off) winc += n;
        }
        warpsums[lane] = winc - ws;   // exclusive warp offset
    }
    __syncthreads();
    int base = warpsums[wid] + (inc - lsum);
    int4 o;
    o.x = base;
    o.y = base + h.x;
    o.z = base + h.x + h.y;
    o.w = base + h.x + h.y + h.z;
    reinterpret_cast<int4*>(g_cur)[t] = o;
}

// K3: scatter into bucket-sorted arrays (spread global atomics)
__global__ __launch_bounds__(256)
void scatter_kernel() {
    int j = blockIdx.x * 256 + threadIdx.x;
    int pos = atomicAdd(&g_cur[g_bk[j]], 1);
    g_ss[pos]  = g_s[j];
    g_ws[pos]  = g_wm[j];
    g_idx[pos] = j;
}

// K4: per-chunk stats + single-warp suffix scan of the three bound arrays
__global__ __launch_bounds__(256)
void bounds_kernel() {
    __shared__ float cmn[NCHUNK], cwx[NCHUNK], cns[NCHUNK];
    const int t = threadIdx.x, lane = t & 31;

    float mn = 3.0e38f, mx = -3.0e38f, ns = -3.0e38f;
    #pragma unroll 8
    for (int q = 0; q < 32; q++) {
        float s = g_ss[t * 32 + q];
        float w = g_ws[t * 32 + q];
        mn = fminf(mn, s);
        mx = fmaxf(mx, w);
        ns = fmaxf(ns, -s * w);
    }
    cmn[t] = mn; cwx[t] = mx; cns[t] = ns;
    __syncthreads();

    if (t < 32) {
        float lm[8], lw[8], ln[8];
        float amn = 3.0e38f, amx = -3.0e38f, ans = -3.0e38f;
        #pragma unroll
        for (int q = 0; q < 8; q++) {
            lm[q] = cmn[t * 8 + q];
            lw[q] = cwx[t * 8 + q];
            ln[q] = cns[t * 8 + q];
            amn = fminf(amn, lm[q]);
            amx = fmaxf(amx, lw[q]);
            ans = fmaxf(ans, ln[q]);
        }
        float smn = amn, smx = amx, sns = ans;
        #pragma unroll
        for (int off = 1; off < 32; off <<= 1) {
            float a = __shfl_down_sync(0xffffffffu, smn, off);
            float b = __shfl_down_sync(0xffffffffu, smx, off);
            float c = __shfl_down_sync(0xffffffffu, sns, off);
            if (lane + off < 32) {
                smn = fminf(smn, a); smx = fmaxf(smx, b); sns = fmaxf(sns, c);
            }
        }
        float tmn = __shfl_down_sync(0xffffffffu, smn, 1);
        float tmx = __shfl_down_sync(0xffffffffu, smx, 1);
        float tns = __shfl_down_sync(0xffffffffu, sns, 1);
        if (lane == 31) { tmn = 3.0e38f; tmx = -3.0e38f; tns = -3.0e38f; }
        float rmn = tmn, rmx = tmx, rns = tns;
        #pragma unroll
        for (int q = 7; q >= 0; q--) {
            rmn = fminf(rmn, lm[q]);
            rmx = fmaxf(rmx, lw[q]);
            rns = fmaxf(rns, ln[q]);
            g_cmin[t * 8 + q] = rmn;
            g_cwub[t * 8 + q] = rmx;
            g_cnsw[t * 8 + q] = rns;
        }
    }
}

// K5: warp per row — 32 candidates/iter, prefetch next chunk, dual safe bound
__global__ __launch_bounds__(256)
void probe_kernel(const int* __restrict__ adj, float* __restrict__ out) {
    const int lane = threadIdx.x & 31;
    const int warp = threadIdx.x >> 5;
    const int i = blockIdx.x * 8 + warp;

    const float si = g_s[i];
    const int* __restrict__ arow = adj + (size_t)i * NN;

    float best = 0.0f;   // reference max always includes T[i,i] = 0

    int a = __ldg(&arow[g_idx[lane]]);

    for (int c = 0; c < NCHUNK; c++) {
        // Prefetch next chunk's adjacency before the reduce (hides DRAM latency)
        int na = 0;
        if (c + 1 < NCHUNK)
            na = __ldg(&arow[g_idx[(c + 1) * 32 + lane]]);

        const int k = c * 32 + lane;
        float d = si - g_ss[k];
        float contrib = (d > 0.0f && a) ? d * g_ws[k] : 0.0f;

        #pragma unroll
        for (int off = 16; off; off >>= 1)
            contrib = fmaxf(contrib, __shfl_xor_sync(0xffffffffu, contrib, off));
        best = fmaxf(best, contrib);

        if (c + 1 < NCHUNK) {
            // Two safe upper bounds on all candidates in chunks >= c+1:
            //  b1: (si - min s) * max w      (fp-monotone, exact-safe)
            //  b2: si*max(w) + max(-s*w) + slack (slack >> total rounding error)
            float b1 = (si - g_cmin[c + 1]) * g_cwub[c + 1];
            float b2 = si * g_cwub[c + 1] + g_cnsw[c + 1] + 1e-5f;
            if (fminf(b1, b2) <= best) break;
            a = na;
        }
    }

    if (lane == 0) {
        out[i * 3 + 0] = best;
        out[i * 3 + 1] = best;
        out[i * 3 + 2] = best;
    }
}

extern "C" void kernel_launch(void* const* d_in, const int* in_sizes, int n_in,
                              void* d_out, int out_size) {
    const float* x    = (const float*)d_in[0];
    const int*   adj  = (const int*)d_in[1];
    const float* Wphi = (const float*)d_in[2];
    // d_in[3] (W_theta) is unused in the forward pass.
    float* out = (float*)d_out;

    zero_hist_kernel<<<KB / 256, 256>>>();
    bucket_kernel<<<NN / 256, 256>>>(x, Wphi);
    scan_kernel<<<1, 1024>>>();
    scatter_kernel<<<NN / 256, 256>>>();
    bounds_kernel<<<1, 256>>>();
    probe_kernel<<<NN / 8, 256>>>(adj, out);
}